// round 9
// baseline (speedup 1.0000x reference)
#include <cuda_runtime.h>
#include <cstdint>

#define HH 192
#define WW 192
#define BB 4
#define HWW (HH*WW)

// ---------------- scratch buffers (device globals; no allocation) ----------
__device__ float g_c1a[BB*64*HWW];
__device__ float g_c1b[BB*64*HWW];
__device__ float g_c2a[BB*128*HWW];
__device__ float g_c2b[BB*128*HWW];
__device__ float g_redir[BB*32*HWW];
__device__ float g_corr[BB*441*HWW];

__device__ __forceinline__ float lrelu(float x) { return x >= 0.f ? x : 0.1f * x; }

__device__ __forceinline__ void cp_async4(uint32_t dst, const void* src, bool p) {
    asm volatile("cp.async.ca.shared.global [%0], [%1], 4, %2;"
                 :: "r"(dst), "l"(src), "r"(p ? 4 : 0));
}
__device__ __forceinline__ void cp_commit() {
    asm volatile("cp.async.commit_group;");
}
__device__ __forceinline__ void cp_wait0() {
    asm volatile("cp.async.wait_group 0;");
}

// ---------------- 3x3 conv + bias + leaky relu (v4, dual-tensor) ------------
// Block 16x16 threads, 3 blocks/SM. Output tile: 32x32 px x 8 co.
// One launch covers BOTH input tensors (pred/ref): blockIdx.z selects.
#define SIN4 (4*34*36)       // floats per input buffer (4896)

template<int CIN, int COUT>
__global__ __launch_bounds__(256, 3)
void conv3x3_dual(const float* __restrict__ in0, const float* __restrict__ in1,
                  const float* __restrict__ wgt, const float* __restrict__ bias,
                  float* __restrict__ out0, float* __restrict__ out1)
{
    extern __shared__ float smem[];   // [2*SIN4 inputs][CIN*72 weights]
    float* s_w = smem + 2*SIN4;

    const int x0 = blockIdx.x * 32;
    const int y0 = blockIdx.y * 32;
    int bz = blockIdx.z;
    const int half_grid = BB * (COUT/8);
    const int pair = bz / half_grid;           // 0 -> in0/out0, 1 -> in1/out1
    bz -= pair * half_grid;
    const float* in  = pair ? in1  : in0;
    float*       out = pair ? out1 : out0;
    const int b   = bz / (COUT/8);
    const int co0 = (bz % (COUT/8)) * 8;
    const int tx = threadIdx.x, ty = threadIdx.y;
    const int tid = ty*16 + tx;

    uint32_t smem_u32 = (uint32_t)__cvta_generic_to_shared(smem);

    // --- precompute input staging slots (1156 positions, <=5 per thread) ---
    int  soff[5];  int goff[5];
    bool inb[5];   bool wr[5];
#pragma unroll
    for (int k = 0; k < 5; k++) {
        int i = tid + k*256;
        bool ok = (i < 34*34);
        int ii = ok ? i : 0;
        int ly = ii / 34, lx = ii % 34;
        int gy = y0 + ly - 1, gx = x0 + lx - 1;
        bool v = ok && (gy >= 0) && (gy < HH) && (gx >= 0) && (gx < WW);
        soff[k] = ly*36 + lx;
        goff[k] = v ? ((b*CIN)*HH + gy)*WW + gx : 0;
        inb[k]  = v;
        wr[k]   = ok;
    }

    auto stage = [&](int buf, int c0) {
        uint32_t in_dst = smem_u32 + buf*(SIN4*4);
#pragma unroll
        for (int k = 0; k < 5; k++) {
            if (wr[k]) {
                const float* src = in + goff[k] + c0*HWW;
                uint32_t d = in_dst + soff[k]*4;
#pragma unroll
                for (int c = 0; c < 4; c++)
                    cp_async4(d + c*(34*36*4), src + c*HWW, inb[k]);
            }
        }
        cp_commit();
    };

    stage(0, 0);

    // pre-stage ALL weights for this co-group: s_w[c][k][o], c<CIN,k<9,o<8
    for (int i = tid; i < CIN*72; i += 256) {
        int c = i / 72, r = i % 72;
        int k = r / 8,  o = r % 8;
        s_w[i] = wgt[((co0 + o)*CIN + c)*9 + k];
    }

    float acc[8][2][2];
#pragma unroll
    for (int o = 0; o < 8; o++)
#pragma unroll
        for (int py = 0; py < 2; py++)
#pragma unroll
            for (int px = 0; px < 2; px++) acc[o][py][px] = 0.f;

    const int NCH = CIN/4;
    for (int ci = 0; ci < NCH; ci++) {
        cp_wait0();
        __syncthreads();
        if (ci + 1 < NCH) stage((ci+1) & 1, (ci+1)*4);

        const float* s_in = smem + (ci & 1)*SIN4;
        const float* wbase = s_w + ci*4*72;

#pragma unroll
        for (int c = 0; c < 4; c++) {
            float p[4][4];
#pragma unroll
            for (int r = 0; r < 4; r++)
#pragma unroll
                for (int q = 0; q < 4; q++)
                    p[r][q] = s_in[c*(34*36) + (ty*2 + r)*36 + tx*2 + q];
#pragma unroll
            for (int ky = 0; ky < 3; ky++) {
#pragma unroll
                for (int kx = 0; kx < 3; kx++) {
                    const float4 wa = *(const float4*)&wbase[c*72 + (ky*3+kx)*8 + 0];
                    const float4 wb = *(const float4*)&wbase[c*72 + (ky*3+kx)*8 + 4];
                    const float w[8] = {wa.x, wa.y, wa.z, wa.w, wb.x, wb.y, wb.z, wb.w};
#pragma unroll
                    for (int py = 0; py < 2; py++) {
#pragma unroll
                        for (int px = 0; px < 2; px++) {
                            const float v = p[py+ky][px+kx];
#pragma unroll
                            for (int o = 0; o < 8; o++)
                                acc[o][py][px] += v * w[o];
                        }
                    }
                }
            }
        }
    }

#pragma unroll
    for (int o = 0; o < 8; o++) {
        const float bv = __ldg(&bias[co0 + o]);
#pragma unroll
        for (int py = 0; py < 2; py++) {
            const int y = y0 + ty*2 + py;
            const int x = x0 + tx*2;
            float2 v;
            v.x = lrelu(acc[o][py][0] + bv);
            v.y = lrelu(acc[o][py][1] + bv);
            *(float2*)&out[(((b*COUT) + co0 + o)*HH + y)*WW + x] = v;
        }
    }
}

// ---------------- 1x1 redir conv + lrelu -----------------------------------
__global__ __launch_bounds__(256)
void redir_conv(const float* __restrict__ in, const float* __restrict__ wgt,
                const float* __restrict__ bias, float* __restrict__ out)
{
    const int b  = blockIdx.y;
    const int p0 = blockIdx.x * 64;
    const int tid = threadIdx.x;

    __shared__ float s[128*64];
    for (int i = tid; i < 128*64; i += 256) {
        int c = i >> 6, p = i & 63;
        s[c*64 + p] = in[(b*128 + c)*HWW + p0 + p];
    }
    __syncthreads();

    for (int oi = tid; oi < 32*64; oi += 256) {
        const int co = oi >> 6;
        const int p  = oi & 63;
        float sum = bias[co];
#pragma unroll 16
        for (int c = 0; c < 128; c++)
            sum += s[c*64 + p] * __ldg(&wgt[co*128 + c]);
        out[(b*32 + co)*HWW + p0 + p] = lrelu(sum);
    }
}

// ---------------- correlation (patch 21, dil 2) + lrelu (v5) ----------------
// Channel-halved smem: sA[64][192] + sB[64][240] = 110.6 KB -> 2 blocks/SM.
// Block = one (b,y) row, 288 threads (9 warps); 18 warps/SM total.
// Per dy: accumulate both 64-channel halves into registers (ping-pong half
// order so the resident A half is reused -> A restaged ~once per dy).
// Lane tile: 8 px x 8 dx over 16 channels; shfl-combine 4 lane-quarters.
#define SBW 60     // float4 per B row (240 floats)
#define SAW 48     // float4 per A row (192 floats)
__device__ __forceinline__ int SWZ(int v) { return v ^ ((v >> 3) & 1); }

__global__ __launch_bounds__(288, 2)
void corr_v5(const float* __restrict__ A, const float* __restrict__ Bm,
             float* __restrict__ out)
{
    extern __shared__ float smem[];
    float4* sA4 = (float4*)smem;                   // [64][SAW]
    float4* sB4 = (float4*)(smem + 64*192);        // [64][SBW] (u -> gx = u-20)

    const int y = blockIdx.x;
    const int b = blockIdx.y;
    const int tid = threadIdx.x;
    const int warp = tid >> 5;
    const int lane = tid & 31;
    const int cq  = lane >> 3;         // channel sixteenth-group 0..3 (16 ch)
    const int sub = lane & 7;          // px sub-tile 0..7
    const int dxg   = warp % 3;        // dx group: 0..7, 8..15, 16..20
    const int pxblk = warp / 3;        // 3 blocks of 64 px
    const int px0 = pxblk*64 + sub*8;
    const int dx0 = dxg*8;
    const int va  = 16*pxblk + 2*sub;  // A float4 base within row
    const int vb  = va + 4*dxg;        // B float4 base within row
    const int cbase = cq*16;

    const float inv_c = 1.0f / 128.0f;
    const float* Ab = A  + (b*128)*HWW + y*WW;
    const float* Bb = Bm + (b*128)*HWW;

    int curA = -1;   // which channel half currently staged in sA

    for (int dy = 0; dy < 21; dy++) {
        const int ry = y + dy*2 - 20;
        if (ry < 0 || ry >= HH) {
            const float4 z = {0.f, 0.f, 0.f, 0.f};
            for (int i = tid; i < 21*48; i += 288) {
                int dx = i / 48, v = i % 48;
                *(float4*)&out[((b*441 + dy*21 + dx)*HH + y)*WW + v*4] = z;
            }
            continue;
        }

        float acc[8][8];
#pragma unroll
        for (int d = 0; d < 8; d++)
#pragma unroll
            for (int p = 0; p < 8; p++) acc[d][p] = 0.f;

        const int first = (curA == 1) ? 1 : 0;   // start with resident half
#pragma unroll
        for (int t = 0; t < 2; t++) {
            const int h = first ^ t;
            __syncthreads();      // previous readers done before overwrite
            if (h != curA) {
                // stage A half: 64 x 48 float4
                const float* Ah = Ab + (h*64)*HWW;
                for (int i = tid; i < 64*SAW; i += 288) {
                    int c = i / SAW, v = i % SAW;
                    sA4[c*SAW + SWZ(v)] = *(const float4*)(Ah + c*HWW + v*4);
                }
                curA = h;
            }
            // stage B half row: 64 x 60 float4
            {
                const float* Brow = Bb + (h*64)*HWW + ry*WW;
                for (int i = tid; i < 64*SBW; i += 288) {
                    int c = i / SBW, v = i % SBW;
                    int gx = v*4 - 20;
                    float4 val;
                    if (gx >= 0 && gx + 3 < WW) {
                        val = *(const float4*)(Brow + c*HWW + gx);
                    } else {
                        val.x = (gx+0 >= 0 && gx+0 < WW) ? Brow[c*HWW + gx+0] : 0.f;
                        val.y = (gx+1 >= 0 && gx+1 < WW) ? Brow[c*HWW + gx+1] : 0.f;
                        val.z = (gx+2 >= 0 && gx+2 < WW) ? Brow[c*HWW + gx+2] : 0.f;
                        val.w = (gx+3 >= 0 && gx+3 < WW) ? Brow[c*HWW + gx+3] : 0.f;
                    }
                    sB4[c*SBW + SWZ(v)] = val;
                }
            }
            __syncthreads();

            const float4* pa = sA4 + cbase*SAW;
            const float4* pb = sB4 + cbase*SBW;
#pragma unroll 2
            for (int cc = 0; cc < 16; cc++) {
                const float4 a0 = pa[cc*SAW + SWZ(va)];
                const float4 a1 = pa[cc*SAW + SWZ(va+1)];
                const float a[8] = {a0.x,a0.y,a0.z,a0.w, a1.x,a1.y,a1.z,a1.w};
                float bv[24];
#pragma unroll
                for (int j = 0; j < 6; j++) {
                    const float4 tt = pb[cc*SBW + SWZ(vb + j)];
                    bv[4*j+0] = tt.x; bv[4*j+1] = tt.y; bv[4*j+2] = tt.z; bv[4*j+3] = tt.w;
                }
#pragma unroll
                for (int d = 0; d < 8; d++)
#pragma unroll
                    for (int p = 0; p < 8; p++)
                        acc[d][p] += a[p] * bv[2*d + p];
            }
        }

        // combine 4 lane-quarter partials (lanes l, l+8, l+16, l+24)
#pragma unroll
        for (int d = 0; d < 8; d++)
#pragma unroll
            for (int p = 0; p < 8; p++) {
                float v = acc[d][p];
                v += __shfl_down_sync(0xffffffffu, v, 16);
                v += __shfl_down_sync(0xffffffffu, v, 8);
                acc[d][p] = v;
            }

        if (cq == 0) {
#pragma unroll
            for (int d = 0; d < 8; d++) {
                const int dx = dx0 + d;
                if (dx < 21) {
                    float* o = &out[((b*441 + dy*21 + dx)*HH + y)*WW + px0];
                    float4 v0, v1;
                    v0.x = lrelu(acc[d][0] * inv_c);
                    v0.y = lrelu(acc[d][1] * inv_c);
                    v0.z = lrelu(acc[d][2] * inv_c);
                    v0.w = lrelu(acc[d][3] * inv_c);
                    v1.x = lrelu(acc[d][4] * inv_c);
                    v1.y = lrelu(acc[d][5] * inv_c);
                    v1.z = lrelu(acc[d][6] * inv_c);
                    v1.w = lrelu(acc[d][7] * inv_c);
                    *(float4*)(o)     = v0;
                    *(float4*)(o + 4) = v1;
                }
            }
        }
    }
}

// ---------------- final 3x3 conv over concat(redir(32), corr(441)) ----------
__global__ __launch_bounds__(256)
void final_conv_v2(const float* __restrict__ redir, const float* __restrict__ corr,
                   const float* __restrict__ wgt, float* __restrict__ out)
{
    const int x0 = blockIdx.x * 32;
    const int y0 = blockIdx.y * 32;
    const int b  = blockIdx.z;
    const int tx = threadIdx.x, ty = threadIdx.y;
    const int tid = ty*16 + tx;

    __shared__ float s[8][34][36];
    __shared__ float sw[8][9][2];

    int  soff[5];  int spat[5];
    bool inb[5];   bool wr[5];
#pragma unroll
    for (int k = 0; k < 5; k++) {
        int i = tid + k*256;
        bool ok = (i < 34*34);
        int ii = ok ? i : 0;
        int ly = ii / 34, lx = ii % 34;
        int gy = y0 + ly - 1, gx = x0 + lx - 1;
        bool v = ok && (gy >= 0) && (gy < HH) && (gx >= 0) && (gx < WW);
        soff[k] = ly*36 + lx;
        spat[k] = v ? gy*WW + gx : 0;
        inb[k]  = v;
        wr[k]   = ok;
    }

    float acc[2][2][2];
#pragma unroll
    for (int o = 0; o < 2; o++)
#pragma unroll
        for (int py = 0; py < 2; py++)
#pragma unroll
            for (int px = 0; px < 2; px++) acc[o][py][px] = 0.f;

    for (int c0 = 0; c0 < 473; c0 += 8) {
        const int cn = (473 - c0) < 8 ? (473 - c0) : 8;
        const float* base = (c0 < 32) ? (redir + (b*32 + c0)*HWW)
                                      : (corr + (b*441 + (c0 - 32))*HWW);
        __syncthreads();
#pragma unroll
        for (int k = 0; k < 5; k++) {
            if (wr[k]) {
                float* sp = &s[0][0][0] + soff[k];
                if (inb[k]) {
                    const float* p = base + spat[k];
                    for (int c = 0; c < cn; c++) sp[c*(34*36)] = p[c*HWW];
                    for (int c = cn; c < 8; c++) sp[c*(34*36)] = 0.f;
                } else {
#pragma unroll
                    for (int c = 0; c < 8; c++) sp[c*(34*36)] = 0.f;
                }
            }
        }
        for (int i = tid; i < cn*18; i += 256) {
            int c = i / 18, r = i % 18;
            int kk = r / 2, o = r % 2;
            sw[c][kk][o] = wgt[(o*473 + c0 + c)*9 + kk];
        }
        for (int i = tid + cn*18; i < 8*18; i += 256) {
            int c = i / 18, r = i % 18;
            sw[c][r/2][r%2] = 0.f;
        }
        __syncthreads();

#pragma unroll
        for (int c = 0; c < 8; c++) {
            float p[4][4];
#pragma unroll
            for (int r = 0; r < 4; r++)
#pragma unroll
                for (int q = 0; q < 4; q++)
                    p[r][q] = s[c][ty*2 + r][tx*2 + q];
#pragma unroll
            for (int ky = 0; ky < 3; ky++) {
#pragma unroll
                for (int kx = 0; kx < 3; kx++) {
                    const float w0 = sw[c][ky*3+kx][0];
                    const float w1 = sw[c][ky*3+kx][1];
#pragma unroll
                    for (int py = 0; py < 2; py++) {
#pragma unroll
                        for (int px = 0; px < 2; px++) {
                            const float v = p[py+ky][px+kx];
                            acc[0][py][px] += v * w0;
                            acc[1][py][px] += v * w1;
                        }
                    }
                }
            }
        }
    }

#pragma unroll
    for (int o = 0; o < 2; o++) {
#pragma unroll
        for (int py = 0; py < 2; py++) {
            const int y = y0 + ty*2 + py;
            const int x = x0 + tx*2;
            float2 v;
            v.x = acc[o][py][0];
            v.y = acc[o][py][1];
            *(float2*)&out[((b*2 + o)*HH + y)*WW + x] = v;
        }
    }
}

// ---------------- launch -----------------------------------------------------
extern "C" void kernel_launch(void* const* d_in, const int* in_sizes, int n_in,
                              void* d_out, int out_size)
{
    const float* pred    = (const float*)d_in[0];
    const float* ref     = (const float*)d_in[1];
    const float* conv1_w = (const float*)d_in[2];
    const float* conv1_b = (const float*)d_in[3];
    const float* conv2_w = (const float*)d_in[4];
    const float* conv2_b = (const float*)d_in[5];
    const float* redir_w = (const float*)d_in[6];
    const float* redir_b = (const float*)d_in[7];
    const float* pred_w  = (const float*)d_in[8];
    float* out = (float*)d_out;

    float *c1a, *c1b, *c2a, *c2b, *rdr, *cor;
    cudaGetSymbolAddress((void**)&c1a, g_c1a);
    cudaGetSymbolAddress((void**)&c1b, g_c1b);
    cudaGetSymbolAddress((void**)&c2a, g_c2a);
    cudaGetSymbolAddress((void**)&c2b, g_c2b);
    cudaGetSymbolAddress((void**)&rdr, g_redir);
    cudaGetSymbolAddress((void**)&cor, g_corr);

    const int conv_smem = (2*SIN4 + 64*72) * (int)sizeof(float); // 57600
    cudaFuncSetAttribute(conv3x3_dual<64,64>,  cudaFuncAttributeMaxDynamicSharedMemorySize, conv_smem);
    cudaFuncSetAttribute(conv3x3_dual<64,128>, cudaFuncAttributeMaxDynamicSharedMemorySize, conv_smem);

    // conv1 (64->64) on pred AND ref in one launch
    {
        dim3 grid(WW/32, HH/32, BB * (64/8) * 2);
        dim3 blk(16, 16);
        conv3x3_dual<64,64><<<grid, blk, conv_smem>>>(pred, ref, conv1_w, conv1_b, c1a, c1b);
    }
    // conv2 (64->128) on both in one launch
    {
        dim3 grid(WW/32, HH/32, BB * (128/8) * 2);
        dim3 blk(16, 16);
        conv3x3_dual<64,128><<<grid, blk, conv_smem>>>(c1a, c1b, conv2_w, conv2_b, c2a, c2b);
    }
    // redir 1x1 (128->32)
    {
        dim3 grid(HWW/64, BB);
        redir_conv<<<grid, 256>>>(c2a, redir_w, redir_b, rdr);
    }
    // correlation
    {
        const int smem_bytes = (64*192 + 64*240) * (int)sizeof(float); // 110592
        cudaFuncSetAttribute(corr_v5, cudaFuncAttributeMaxDynamicSharedMemorySize, smem_bytes);
        dim3 grid(HH, BB);
        corr_v5<<<grid, 288, smem_bytes>>>(c2a, c2b, cor);
    }
    // final conv (473->2)
    {
        dim3 grid(WW/32, HH/32, BB);
        dim3 blk(16, 16);
        final_conv_v2<<<grid, blk>>>(rdr, cor, pred_w, out);
    }
}

// round 10
// speedup vs baseline: 1.7436x; 1.7436x over previous
#include <cuda_runtime.h>
#include <cstdint>

#define HH 192
#define WW 192
#define BB 4
#define HWW (HH*WW)

// ---------------- scratch buffers (device globals; no allocation) ----------
__device__ float g_c1a[BB*64*HWW];
__device__ float g_c1b[BB*64*HWW];
__device__ float g_c2a[BB*128*HWW];
__device__ float g_c2b[BB*128*HWW];
__device__ float g_redir[BB*32*HWW];
__device__ float g_corr[BB*441*HWW];

__device__ __forceinline__ float lrelu(float x) { return x >= 0.f ? x : 0.1f * x; }

__device__ __forceinline__ void cp_async4(uint32_t dst, const void* src, bool p) {
    asm volatile("cp.async.ca.shared.global [%0], [%1], 4, %2;"
                 :: "r"(dst), "l"(src), "r"(p ? 4 : 0));
}
__device__ __forceinline__ void cp_async16(uint32_t dst, const void* src, bool p) {
    asm volatile("cp.async.cg.shared.global [%0], [%1], 16, %2;"
                 :: "r"(dst), "l"(src), "r"(p ? 16 : 0));
}
__device__ __forceinline__ void cp_commit() {
    asm volatile("cp.async.commit_group;");
}
__device__ __forceinline__ void cp_wait0() {
    asm volatile("cp.async.wait_group 0;");
}

// ---------------- 3x3 conv + bias + leaky relu (v4, round-5 proven) ---------
// Block 16x16 threads, 3 blocks/SM. Output tile: 32x32 px x 8 co.
#define SIN4 (4*34*36)       // floats per input buffer (4896)

template<int CIN, int COUT>
__global__ __launch_bounds__(256, 3)
void conv3x3_v4(const float* __restrict__ in, const float* __restrict__ wgt,
                const float* __restrict__ bias, float* __restrict__ out)
{
    extern __shared__ float smem[];   // [2*SIN4 inputs][CIN*72 weights]
    float* s_w = smem + 2*SIN4;

    const int x0 = blockIdx.x * 32;
    const int y0 = blockIdx.y * 32;
    const int bz = blockIdx.z;
    const int b   = bz / (COUT/8);
    const int co0 = (bz % (COUT/8)) * 8;
    const int tx = threadIdx.x, ty = threadIdx.y;
    const int tid = ty*16 + tx;

    uint32_t smem_u32 = (uint32_t)__cvta_generic_to_shared(smem);

    int  soff[5];  int goff[5];
    bool inb[5];   bool wr[5];
#pragma unroll
    for (int k = 0; k < 5; k++) {
        int i = tid + k*256;
        bool ok = (i < 34*34);
        int ii = ok ? i : 0;
        int ly = ii / 34, lx = ii % 34;
        int gy = y0 + ly - 1, gx = x0 + lx - 1;
        bool v = ok && (gy >= 0) && (gy < HH) && (gx >= 0) && (gx < WW);
        soff[k] = ly*36 + lx;
        goff[k] = v ? ((b*CIN)*HH + gy)*WW + gx : 0;
        inb[k]  = v;
        wr[k]   = ok;
    }

    auto stage = [&](int buf, int c0) {
        uint32_t in_dst = smem_u32 + buf*(SIN4*4);
#pragma unroll
        for (int k = 0; k < 5; k++) {
            if (wr[k]) {
                const float* src = in + goff[k] + c0*HWW;
                uint32_t d = in_dst + soff[k]*4;
#pragma unroll
                for (int c = 0; c < 4; c++)
                    cp_async4(d + c*(34*36*4), src + c*HWW, inb[k]);
            }
        }
        cp_commit();
    };

    stage(0, 0);

    for (int i = tid; i < CIN*72; i += 256) {
        int c = i / 72, r = i % 72;
        int k = r / 8,  o = r % 8;
        s_w[i] = wgt[((co0 + o)*CIN + c)*9 + k];
    }

    float acc[8][2][2];
#pragma unroll
    for (int o = 0; o < 8; o++)
#pragma unroll
        for (int py = 0; py < 2; py++)
#pragma unroll
            for (int px = 0; px < 2; px++) acc[o][py][px] = 0.f;

    const int NCH = CIN/4;
    for (int ci = 0; ci < NCH; ci++) {
        cp_wait0();
        __syncthreads();
        if (ci + 1 < NCH) stage((ci+1) & 1, (ci+1)*4);

        const float* s_in = smem + (ci & 1)*SIN4;
        const float* wbase = s_w + ci*4*72;

#pragma unroll
        for (int c = 0; c < 4; c++) {
            float p[4][4];
#pragma unroll
            for (int r = 0; r < 4; r++)
#pragma unroll
                for (int q = 0; q < 4; q++)
                    p[r][q] = s_in[c*(34*36) + (ty*2 + r)*36 + tx*2 + q];
#pragma unroll
            for (int ky = 0; ky < 3; ky++) {
#pragma unroll
                for (int kx = 0; kx < 3; kx++) {
                    const float4 wa = *(const float4*)&wbase[c*72 + (ky*3+kx)*8 + 0];
                    const float4 wb = *(const float4*)&wbase[c*72 + (ky*3+kx)*8 + 4];
                    const float w[8] = {wa.x, wa.y, wa.z, wa.w, wb.x, wb.y, wb.z, wb.w};
#pragma unroll
                    for (int py = 0; py < 2; py++) {
#pragma unroll
                        for (int px = 0; px < 2; px++) {
                            const float v = p[py+ky][px+kx];
#pragma unroll
                            for (int o = 0; o < 8; o++)
                                acc[o][py][px] += v * w[o];
                        }
                    }
                }
            }
        }
    }

#pragma unroll
    for (int o = 0; o < 8; o++) {
        const float bv = __ldg(&bias[co0 + o]);
#pragma unroll
        for (int py = 0; py < 2; py++) {
            const int y = y0 + ty*2 + py;
            const int x = x0 + tx*2;
            float2 v;
            v.x = lrelu(acc[o][py][0] + bv);
            v.y = lrelu(acc[o][py][1] + bv);
            *(float2*)&out[(((b*COUT) + co0 + o)*HH + y)*WW + x] = v;
        }
    }
}

// ---------------- 1x1 redir conv + lrelu -----------------------------------
__global__ __launch_bounds__(256)
void redir_conv(const float* __restrict__ in, const float* __restrict__ wgt,
                const float* __restrict__ bias, float* __restrict__ out)
{
    const int b  = blockIdx.y;
    const int p0 = blockIdx.x * 64;
    const int tid = threadIdx.x;

    __shared__ float s[128*64];
    for (int i = tid; i < 128*64; i += 256) {
        int c = i >> 6, p = i & 63;
        s[c*64 + p] = in[(b*128 + c)*HWW + p0 + p];
    }
    __syncthreads();

    for (int oi = tid; oi < 32*64; oi += 256) {
        const int co = oi >> 6;
        const int p  = oi & 63;
        float sum = bias[co];
#pragma unroll 16
        for (int c = 0; c < 128; c++)
            sum += s[c*64 + p] * __ldg(&wgt[co*128 + c]);
        out[(b*32 + co)*HWW + p0 + p] = lrelu(sum);
    }
}

// ---------------- correlation (patch 21, dil 2) + lrelu (v6) ----------------
// Same mapping as proven corr_v4 (288 thr, lane tile 8px x 8dx, SWZ smem),
// but B is staged per-dy in 4 x 32-channel chunks, double-buffered with
// cp.async so DMA of chunk j+1 overlaps compute of chunk j. A staged once
// via cp.async. smem: A[128][192] + 2 x B[32][240] = 160 KB.
#define SBW 60     // float4 per B row (240 floats)
#define SAW 48     // float4 per A row (192 floats)
#define SA_FLOATS (128*192)
#define SBUF_FLOATS (32*240)
__device__ __forceinline__ int SWZ(int v) { return v ^ ((v >> 3) & 1); }

__global__ __launch_bounds__(288)
void corr_v6(const float* __restrict__ A, const float* __restrict__ Bm,
             float* __restrict__ out)
{
    extern __shared__ float smem[];
    float4* sA4 = (float4*)smem;                       // [128][SAW]
    // chunk buffers: smem + SA_FLOATS + buf*SBUF_FLOATS, layout [32][SBW] f4

    const int y = blockIdx.x;
    const int b = blockIdx.y;
    const int tid = threadIdx.x;
    const int warp = tid >> 5;
    const int lane = tid & 31;
    const int cq  = lane >> 3;         // channel quarter within chunk (8 ch)
    const int sub = lane & 7;          // px sub-tile 0..7
    const int dxg   = warp % 3;        // dx group: 0..7, 8..15, 16..20
    const int pxblk = warp / 3;        // 3 blocks of 64 px
    const int px0 = pxblk*64 + sub*8;
    const int dx0 = dxg*8;
    const int va  = 16*pxblk + 2*sub;  // A float4 base within row
    const int vb  = va + 4*dxg;        // B float4 base within row

    uint32_t smem_u32 = (uint32_t)__cvta_generic_to_shared(smem);
    const uint32_t bbuf_u32[2] = { smem_u32 + SA_FLOATS*4,
                                   smem_u32 + (SA_FLOATS + SBUF_FLOATS)*4 };

    const float inv_c = 1.0f / 128.0f;
    const float* Ab = A  + (b*128)*HWW + y*WW;
    const float* Bb = Bm + (b*128)*HWW;

    // ---- precompute B-chunk staging slots (32*60 = 1920 f4, 7 per thread) --
    int  bdst[7];   // float4 index within chunk buffer (swizzled)
    int  bsrc[7];   // float offset within (Brow + c*HWW) base
    bool bok[7];    // slot active
    bool bin[7];    // in-bounds (else zero-fill)
#pragma unroll
    for (int k = 0; k < 7; k++) {
        int i = tid + k*288;
        bool ok = (i < 32*SBW);
        int ii = ok ? i : 0;
        int c = ii / SBW, v = ii % SBW;
        bool inb = (v >= 5) && (v <= 52);      // gx = 4v-20 fully in [0,192)
        bdst[k] = c*SBW + SWZ(v);
        bsrc[k] = c*HWW + (inb ? 4*v - 20 : 0);
        bok[k]  = ok;
        bin[k]  = inb;
    }

    // ---- stage A once via cp.async (all in-bounds) ----
    for (int i = tid; i < 128*SAW; i += 288) {
        int c = i / SAW, v = i % SAW;
        cp_async16(smem_u32 + (c*SAW + SWZ(v))*16, Ab + c*HWW + v*4, true);
    }
    cp_commit();

    auto stage_chunk = [&](int buf, const float* Brow, int chunk) {
        const float* base = Brow + chunk*32*HWW;
        uint32_t dst = bbuf_u32[buf];
#pragma unroll
        for (int k = 0; k < 7; k++)
            if (bok[k]) cp_async16(dst + bdst[k]*16, base + bsrc[k], bin[k]);
        cp_commit();
    };

    bool pending = false;   // chunk0 of current dy already staged into buf0?

    for (int dy = 0; dy < 21; dy++) {
        const int ry = y + dy*2 - 20;
        if (ry < 0 || ry >= HH) {
            const float4 z = {0.f, 0.f, 0.f, 0.f};
            for (int i = tid; i < 21*48; i += 288) {
                int dx = i / 48, v = i % 48;
                *(float4*)&out[((b*441 + dy*21 + dx)*HH + y)*WW + v*4] = z;
            }
            continue;
        }
        const float* Brow = Bb + ry*WW;
        if (!pending) stage_chunk(0, Brow, 0);

        float acc[8][8];
#pragma unroll
        for (int d = 0; d < 8; d++)
#pragma unroll
            for (int p = 0; p < 8; p++) acc[d][p] = 0.f;

#pragma unroll
        for (int j = 0; j < 4; j++) {
            cp_wait0();          // chunk j (and A, first time) arrived
            __syncthreads();     // all warps done with buf[(j+1)&1]'s old data
            if (j < 3) {
                stage_chunk((j+1) & 1, Brow, j+1);
            } else {
                const int ry2 = ry + 2;
                if (dy < 20 && ry2 < HH) {
                    stage_chunk(0, Bb + ry2*WW, 0);
                    pending = true;
                } else {
                    pending = false;
                }
            }

            const float4* pa = sA4 + (j*32 + cq*8)*SAW;
            const float4* pb = (const float4*)(smem + SA_FLOATS
                               + (j & 1)*SBUF_FLOATS) + (cq*8)*SBW;
#pragma unroll 2
            for (int cc = 0; cc < 8; cc++) {
                const float4 a0 = pa[cc*SAW + SWZ(va)];
                const float4 a1 = pa[cc*SAW + SWZ(va+1)];
                const float a[8] = {a0.x,a0.y,a0.z,a0.w, a1.x,a1.y,a1.z,a1.w};
                float bv[24];
#pragma unroll
                for (int t = 0; t < 6; t++) {
                    const float4 tt = pb[cc*SBW + SWZ(vb + t)];
                    bv[4*t+0] = tt.x; bv[4*t+1] = tt.y;
                    bv[4*t+2] = tt.z; bv[4*t+3] = tt.w;
                }
#pragma unroll
                for (int d = 0; d < 8; d++)
#pragma unroll
                    for (int p = 0; p < 8; p++)
                        acc[d][p] += a[p] * bv[2*d + p];
            }
        }

        // combine 4 lane-quarter partials (lanes l, l+8, l+16, l+24)
#pragma unroll
        for (int d = 0; d < 8; d++)
#pragma unroll
            for (int p = 0; p < 8; p++) {
                float v = acc[d][p];
                v += __shfl_down_sync(0xffffffffu, v, 16);
                v += __shfl_down_sync(0xffffffffu, v, 8);
                acc[d][p] = v;
            }

        if (cq == 0) {
#pragma unroll
            for (int d = 0; d < 8; d++) {
                const int dx = dx0 + d;
                if (dx < 21) {
                    float* o = &out[((b*441 + dy*21 + dx)*HH + y)*WW + px0];
                    float4 v0, v1;
                    v0.x = lrelu(acc[d][0] * inv_c);
                    v0.y = lrelu(acc[d][1] * inv_c);
                    v0.z = lrelu(acc[d][2] * inv_c);
                    v0.w = lrelu(acc[d][3] * inv_c);
                    v1.x = lrelu(acc[d][4] * inv_c);
                    v1.y = lrelu(acc[d][5] * inv_c);
                    v1.z = lrelu(acc[d][6] * inv_c);
                    v1.w = lrelu(acc[d][7] * inv_c);
                    *(float4*)(o)     = v0;
                    *(float4*)(o + 4) = v1;
                }
            }
        }
    }
}

// ---------------- final 3x3 conv over concat(redir(32), corr(441)) ----------
__global__ __launch_bounds__(256)
void final_conv_v2(const float* __restrict__ redir, const float* __restrict__ corr,
                   const float* __restrict__ wgt, float* __restrict__ out)
{
    const int x0 = blockIdx.x * 32;
    const int y0 = blockIdx.y * 32;
    const int b  = blockIdx.z;
    const int tx = threadIdx.x, ty = threadIdx.y;
    const int tid = ty*16 + tx;

    __shared__ float s[8][34][36];
    __shared__ float sw[8][9][2];

    int  soff[5];  int spat[5];
    bool inb[5];   bool wr[5];
#pragma unroll
    for (int k = 0; k < 5; k++) {
        int i = tid + k*256;
        bool ok = (i < 34*34);
        int ii = ok ? i : 0;
        int ly = ii / 34, lx = ii % 34;
        int gy = y0 + ly - 1, gx = x0 + lx - 1;
        bool v = ok && (gy >= 0) && (gy < HH) && (gx >= 0) && (gx < WW);
        soff[k] = ly*36 + lx;
        spat[k] = v ? gy*WW + gx : 0;
        inb[k]  = v;
        wr[k]   = ok;
    }

    float acc[2][2][2];
#pragma unroll
    for (int o = 0; o < 2; o++)
#pragma unroll
        for (int py = 0; py < 2; py++)
#pragma unroll
            for (int px = 0; px < 2; px++) acc[o][py][px] = 0.f;

    for (int c0 = 0; c0 < 473; c0 += 8) {
        const int cn = (473 - c0) < 8 ? (473 - c0) : 8;
        const float* base = (c0 < 32) ? (redir + (b*32 + c0)*HWW)
                                      : (corr + (b*441 + (c0 - 32))*HWW);
        __syncthreads();
#pragma unroll
        for (int k = 0; k < 5; k++) {
            if (wr[k]) {
                float* sp = &s[0][0][0] + soff[k];
                if (inb[k]) {
                    const float* p = base + spat[k];
                    for (int c = 0; c < cn; c++) sp[c*(34*36)] = p[c*HWW];
                    for (int c = cn; c < 8; c++) sp[c*(34*36)] = 0.f;
                } else {
#pragma unroll
                    for (int c = 0; c < 8; c++) sp[c*(34*36)] = 0.f;
                }
            }
        }
        for (int i = tid; i < cn*18; i += 256) {
            int c = i / 18, r = i % 18;
            int kk = r / 2, o = r % 2;
            sw[c][kk][o] = wgt[(o*473 + c0 + c)*9 + kk];
        }
        for (int i = tid + cn*18; i < 8*18; i += 256) {
            int c = i / 18, r = i % 18;
            sw[c][r/2][r%2] = 0.f;
        }
        __syncthreads();

#pragma unroll
        for (int c = 0; c < 8; c++) {
            float p[4][4];
#pragma unroll
            for (int r = 0; r < 4; r++)
#pragma unroll
                for (int q = 0; q < 4; q++)
                    p[r][q] = s[c][ty*2 + r][tx*2 + q];
#pragma unroll
            for (int ky = 0; ky < 3; ky++) {
#pragma unroll
                for (int kx = 0; kx < 3; kx++) {
                    const float w0 = sw[c][ky*3+kx][0];
                    const float w1 = sw[c][ky*3+kx][1];
#pragma unroll
                    for (int py = 0; py < 2; py++) {
#pragma unroll
                        for (int px = 0; px < 2; px++) {
                            const float v = p[py+ky][px+kx];
                            acc[0][py][px] += v * w0;
                            acc[1][py][px] += v * w1;
                        }
                    }
                }
            }
        }
    }

#pragma unroll
    for (int o = 0; o < 2; o++) {
#pragma unroll
        for (int py = 0; py < 2; py++) {
            const int y = y0 + ty*2 + py;
            const int x = x0 + tx*2;
            float2 v;
            v.x = acc[o][py][0];
            v.y = acc[o][py][1];
            *(float2*)&out[((b*2 + o)*HH + y)*WW + x] = v;
        }
    }
}

// ---------------- launch -----------------------------------------------------
extern "C" void kernel_launch(void* const* d_in, const int* in_sizes, int n_in,
                              void* d_out, int out_size)
{
    const float* pred    = (const float*)d_in[0];
    const float* ref     = (const float*)d_in[1];
    const float* conv1_w = (const float*)d_in[2];
    const float* conv1_b = (const float*)d_in[3];
    const float* conv2_w = (const float*)d_in[4];
    const float* conv2_b = (const float*)d_in[5];
    const float* redir_w = (const float*)d_in[6];
    const float* redir_b = (const float*)d_in[7];
    const float* pred_w  = (const float*)d_in[8];
    float* out = (float*)d_out;

    float *c1a, *c1b, *c2a, *c2b, *rdr, *cor;
    cudaGetSymbolAddress((void**)&c1a, g_c1a);
    cudaGetSymbolAddress((void**)&c1b, g_c1b);
    cudaGetSymbolAddress((void**)&c2a, g_c2a);
    cudaGetSymbolAddress((void**)&c2b, g_c2b);
    cudaGetSymbolAddress((void**)&rdr, g_redir);
    cudaGetSymbolAddress((void**)&cor, g_corr);

    const int conv_smem = (2*SIN4 + 64*72) * (int)sizeof(float); // 57600
    cudaFuncSetAttribute(conv3x3_v4<64,64>,  cudaFuncAttributeMaxDynamicSharedMemorySize, conv_smem);
    cudaFuncSetAttribute(conv3x3_v4<64,128>, cudaFuncAttributeMaxDynamicSharedMemorySize, conv_smem);

    // conv1 (64->64) on pred and ref
    {
        dim3 grid(WW/32, HH/32, BB * (64/8));
        dim3 blk(16, 16);
        conv3x3_v4<64,64><<<grid, blk, conv_smem>>>(pred, conv1_w, conv1_b, c1a);
        conv3x3_v4<64,64><<<grid, blk, conv_smem>>>(ref,  conv1_w, conv1_b, c1b);
    }
    // conv2 (64->128)
    {
        dim3 grid(WW/32, HH/32, BB * (128/8));
        dim3 blk(16, 16);
        conv3x3_v4<64,128><<<grid, blk, conv_smem>>>(c1a, conv2_w, conv2_b, c2a);
        conv3x3_v4<64,128><<<grid, blk, conv_smem>>>(c1b, conv2_w, conv2_b, c2b);
    }
    // redir 1x1 (128->32)
    {
        dim3 grid(HWW/64, BB);
        redir_conv<<<grid, 256>>>(c2a, redir_w, redir_b, rdr);
    }
    // correlation
    {
        const int smem_bytes = (SA_FLOATS + 2*SBUF_FLOATS) * (int)sizeof(float); // 159744
        cudaFuncSetAttribute(corr_v6, cudaFuncAttributeMaxDynamicSharedMemorySize, smem_bytes);
        dim3 grid(HH, BB);
        corr_v6<<<grid, 288, smem_bytes>>>(c2a, c2b, cor);
    }
    // final conv (473->2)
    {
        dim3 grid(WW/32, HH/32, BB);
        dim3 blk(16, 16);
        final_conv_v2<<<grid, blk>>>(rdr, cor, pred_w, out);
    }
}

// round 12
// speedup vs baseline: 1.7858x; 1.0242x over previous
#include <cuda_runtime.h>
#include <cstdint>

#define HH 192
#define WW 192
#define BB 4
#define HWW (HH*WW)

// ---------------- scratch buffers (device globals; no allocation) ----------
__device__ float g_c1a[BB*64*HWW];
__device__ float g_c1b[BB*64*HWW];
__device__ float g_c2a[BB*128*HWW];
__device__ float g_c2b[BB*128*HWW];
__device__ float g_redir[BB*32*HWW];
__device__ float g_corr[BB*441*HWW];

__device__ __forceinline__ float lrelu(float x) { return x >= 0.f ? x : 0.1f * x; }

__device__ __forceinline__ void cp_async4(uint32_t dst, const void* src, bool p) {
    asm volatile("cp.async.ca.shared.global [%0], [%1], 4, %2;"
                 :: "r"(dst), "l"(src), "r"(p ? 4 : 0));
}
__device__ __forceinline__ void cp_async16(uint32_t dst, const void* src, bool p) {
    asm volatile("cp.async.cg.shared.global [%0], [%1], 16, %2;"
                 :: "r"(dst), "l"(src), "r"(p ? 16 : 0));
}
__device__ __forceinline__ void cp_commit() {
    asm volatile("cp.async.commit_group;");
}
__device__ __forceinline__ void cp_wait0() {
    asm volatile("cp.async.wait_group 0;");
}

// ---------------- 3x3 conv + bias + leaky relu (v4, proven) -----------------
#define SIN4 (4*34*36)       // floats per input buffer (4896)

template<int CIN, int COUT>
__global__ __launch_bounds__(256, 3)
void conv3x3_v4(const float* __restrict__ in, const float* __restrict__ wgt,
                const float* __restrict__ bias, float* __restrict__ out)
{
    extern __shared__ float smem[];   // [2*SIN4 inputs][CIN*72 weights]
    float* s_w = smem + 2*SIN4;

    const int x0 = blockIdx.x * 32;
    const int y0 = blockIdx.y * 32;
    const int bz = blockIdx.z;
    const int b   = bz / (COUT/8);
    const int co0 = (bz % (COUT/8)) * 8;
    const int tx = threadIdx.x, ty = threadIdx.y;
    const int tid = ty*16 + tx;

    uint32_t smem_u32 = (uint32_t)__cvta_generic_to_shared(smem);

    int  soff[5];  int goff[5];
    bool inb[5];   bool wr[5];
#pragma unroll
    for (int k = 0; k < 5; k++) {
        int i = tid + k*256;
        bool ok = (i < 34*34);
        int ii = ok ? i : 0;
        int ly = ii / 34, lx = ii % 34;
        int gy = y0 + ly - 1, gx = x0 + lx - 1;
        bool v = ok && (gy >= 0) && (gy < HH) && (gx >= 0) && (gx < WW);
        soff[k] = ly*36 + lx;
        goff[k] = v ? ((b*CIN)*HH + gy)*WW + gx : 0;
        inb[k]  = v;
        wr[k]   = ok;
    }

    auto stage = [&](int buf, int c0) {
        uint32_t in_dst = smem_u32 + buf*(SIN4*4);
#pragma unroll
        for (int k = 0; k < 5; k++) {
            if (wr[k]) {
                const float* src = in + goff[k] + c0*HWW;
                uint32_t d = in_dst + soff[k]*4;
#pragma unroll
                for (int c = 0; c < 4; c++)
                    cp_async4(d + c*(34*36*4), src + c*HWW, inb[k]);
            }
        }
        cp_commit();
    };

    stage(0, 0);

    for (int i = tid; i < CIN*72; i += 256) {
        int c = i / 72, r = i % 72;
        int k = r / 8,  o = r % 8;
        s_w[i] = wgt[((co0 + o)*CIN + c)*9 + k];
    }

    float acc[8][2][2];
#pragma unroll
    for (int o = 0; o < 8; o++)
#pragma unroll
        for (int py = 0; py < 2; py++)
#pragma unroll
            for (int px = 0; px < 2; px++) acc[o][py][px] = 0.f;

    const int NCH = CIN/4;
    for (int ci = 0; ci < NCH; ci++) {
        cp_wait0();
        __syncthreads();
        if (ci + 1 < NCH) stage((ci+1) & 1, (ci+1)*4);

        const float* s_in = smem + (ci & 1)*SIN4;
        const float* wbase = s_w + ci*4*72;

#pragma unroll
        for (int c = 0; c < 4; c++) {
            float p[4][4];
#pragma unroll
            for (int r = 0; r < 4; r++)
#pragma unroll
                for (int q = 0; q < 4; q++)
                    p[r][q] = s_in[c*(34*36) + (ty*2 + r)*36 + tx*2 + q];
#pragma unroll
            for (int ky = 0; ky < 3; ky++) {
#pragma unroll
                for (int kx = 0; kx < 3; kx++) {
                    const float4 wa = *(const float4*)&wbase[c*72 + (ky*3+kx)*8 + 0];
                    const float4 wb = *(const float4*)&wbase[c*72 + (ky*3+kx)*8 + 4];
                    const float w[8] = {wa.x, wa.y, wa.z, wa.w, wb.x, wb.y, wb.z, wb.w};
#pragma unroll
                    for (int py = 0; py < 2; py++) {
#pragma unroll
                        for (int px = 0; px < 2; px++) {
                            const float v = p[py+ky][px+kx];
#pragma unroll
                            for (int o = 0; o < 8; o++)
                                acc[o][py][px] += v * w[o];
                        }
                    }
                }
            }
        }
    }

#pragma unroll
    for (int o = 0; o < 8; o++) {
        const float bv = __ldg(&bias[co0 + o]);
#pragma unroll
        for (int py = 0; py < 2; py++) {
            const int y = y0 + ty*2 + py;
            const int x = x0 + tx*2;
            float2 v;
            v.x = lrelu(acc[o][py][0] + bv);
            v.y = lrelu(acc[o][py][1] + bv);
            *(float2*)&out[(((b*COUT) + co0 + o)*HH + y)*WW + x] = v;
        }
    }
}

// ---------------- 1x1 redir conv + lrelu -----------------------------------
__global__ __launch_bounds__(256)
void redir_conv(const float* __restrict__ in, const float* __restrict__ wgt,
                const float* __restrict__ bias, float* __restrict__ out)
{
    const int b  = blockIdx.y;
    const int p0 = blockIdx.x * 64;
    const int tid = threadIdx.x;

    __shared__ float s[128*64];
    for (int i = tid; i < 128*64; i += 256) {
        int c = i >> 6, p = i & 63;
        s[c*64 + p] = in[(b*128 + c)*HWW + p0 + p];
    }
    __syncthreads();

    for (int oi = tid; oi < 32*64; oi += 256) {
        const int co = oi >> 6;
        const int p  = oi & 63;
        float sum = bias[co];
#pragma unroll 16
        for (int c = 0; c < 128; c++)
            sum += s[c*64 + p] * __ldg(&wgt[co*128 + c]);
        out[(b*32 + co)*HWW + p0 + p] = lrelu(sum);
    }
}

// ---------------- correlation (patch 21, dil 2) + lrelu (v7) ----------------
// 288 threads, lane tile 8px x 8dx, SWZ smem (proven v4/v6 mapping).
// B staged per-dy in 2 x 64-channel chunks, double-buffered with cp.async:
// only 2 wait+sync rendezvous per dy (vs 8 in v6). Next dy's first chunk is
// prefetched during the second half. A staged once via cp.async.
// smem: A[128][192] + 2 x B[64][240] = 216 KB.
#define SBW 60     // float4 per B row (240 floats)
#define SAW 48     // float4 per A row (192 floats)
#define SA_FLOATS (128*192)
#define SBUF_FLOATS (64*240)
__device__ __forceinline__ int SWZ(int v) { return v ^ ((v >> 3) & 1); }

__global__ __launch_bounds__(288)
void corr_v7(const float* __restrict__ A, const float* __restrict__ Bm,
             float* __restrict__ out)
{
    extern __shared__ float smem[];
    float4* sA4 = (float4*)smem;                       // [128][SAW]

    const int y = blockIdx.x;
    const int b = blockIdx.y;
    const int tid = threadIdx.x;
    const int warp = tid >> 5;
    const int lane = tid & 31;
    const int cq  = lane >> 3;         // channel quarter within chunk (16 ch)
    const int sub = lane & 7;          // px sub-tile 0..7
    const int dxg   = warp % 3;        // dx group: 0..7, 8..15, 16..20
    const int pxblk = warp / 3;        // 3 blocks of 64 px
    const int px0 = pxblk*64 + sub*8;
    const int dx0 = dxg*8;
    const int va  = 16*pxblk + 2*sub;  // A float4 base within row
    const int vb  = va + 4*dxg;        // B float4 base within row

    uint32_t smem_u32 = (uint32_t)__cvta_generic_to_shared(smem);
    const uint32_t bbuf_u32[2] = { smem_u32 + SA_FLOATS*4,
                                   smem_u32 + (SA_FLOATS + SBUF_FLOATS)*4 };

    const float inv_c = 1.0f / 128.0f;
    const float* Ab = A  + (b*128)*HWW + y*WW;
    const float* Bb = Bm + (b*128)*HWW;

    // ---- stage A once via cp.async (all in-bounds) ----
    for (int i = tid; i < 128*SAW; i += 288) {
        int c = i / SAW, v = i % SAW;
        cp_async16(smem_u32 + (c*SAW + SWZ(v))*16, Ab + c*HWW + v*4, true);
    }
    cp_commit();

    // stage one 64-channel half of a B row into buffer buf
    auto stage_half = [&](int buf, const float* Brow, int half) {
        const float* base = Brow + half*64*HWW;
        uint32_t dst = bbuf_u32[buf];
        for (int i = tid; i < 64*SBW; i += 288) {
            int c = i / SBW, v = i % SBW;
            bool inb = (v >= 5) && (v <= 52);      // gx = 4v-20 fully in range
            cp_async16(dst + (c*SBW + SWZ(v))*16,
                       base + c*HWW + (inb ? 4*v - 20 : 0), inb);
        }
        cp_commit();
    };

    bool pending = false;   // half0 of current dy already staged into buf0?

    for (int dy = 0; dy < 21; dy++) {
        const int ry = y + dy*2 - 20;
        if (ry < 0 || ry >= HH) {
            const float4 z = {0.f, 0.f, 0.f, 0.f};
            for (int i = tid; i < 21*48; i += 288) {
                int dx = i / 48, v = i % 48;
                *(float4*)&out[((b*441 + dy*21 + dx)*HH + y)*WW + v*4] = z;
            }
            continue;
        }
        const float* Brow = Bb + ry*WW;
        if (!pending) stage_half(0, Brow, 0);

        float acc[8][8];
#pragma unroll
        for (int d = 0; d < 8; d++)
#pragma unroll
            for (int p = 0; p < 8; p++) acc[d][p] = 0.f;

#pragma unroll
        for (int j = 0; j < 2; j++) {
            cp_wait0();          // half j (and A, first time) arrived
            __syncthreads();     // all warps done with the buffer we overwrite
            if (j == 0) {
                stage_half(1, Brow, 1);
            } else {
                const int ry2 = ry + 2;
                if (dy < 20 && ry2 < HH) {
                    stage_half(0, Bb + ry2*WW, 0);
                    pending = true;
                } else {
                    pending = false;
                }
            }

            const float4* pa = sA4 + (j*64 + cq*16)*SAW;
            const float4* pb = (const float4*)(smem + SA_FLOATS
                               + j*SBUF_FLOATS) + (cq*16)*SBW;
#pragma unroll 2
            for (int cc = 0; cc < 16; cc++) {
                const float4 a0 = pa[cc*SAW + SWZ(va)];
                const float4 a1 = pa[cc*SAW + SWZ(va+1)];
                const float a[8] = {a0.x,a0.y,a0.z,a0.w, a1.x,a1.y,a1.z,a1.w};
                float bv[24];
#pragma unroll
                for (int t = 0; t < 6; t++) {
                    const float4 tt = pb[cc*SBW + SWZ(vb + t)];
                    bv[4*t+0] = tt.x; bv[4*t+1] = tt.y;
                    bv[4*t+2] = tt.z; bv[4*t+3] = tt.w;
                }
#pragma unroll
                for (int d = 0; d < 8; d++)
#pragma unroll
                    for (int p = 0; p < 8; p++)
                        acc[d][p] += a[p] * bv[2*d + p];
            }
        }

        // combine 4 lane-quarter partials (lanes l, l+8, l+16, l+24)
#pragma unroll
        for (int d = 0; d < 8; d++)
#pragma unroll
            for (int p = 0; p < 8; p++) {
                float v = acc[d][p];
                v += __shfl_down_sync(0xffffffffu, v, 16);
                v += __shfl_down_sync(0xffffffffu, v, 8);
                acc[d][p] = v;
            }

        if (cq == 0) {
#pragma unroll
            for (int d = 0; d < 8; d++) {
                const int dx = dx0 + d;
                if (dx < 21) {
                    float* o = &out[((b*441 + dy*21 + dx)*HH + y)*WW + px0];
                    float4 v0, v1;
                    v0.x = lrelu(acc[d][0] * inv_c);
                    v0.y = lrelu(acc[d][1] * inv_c);
                    v0.z = lrelu(acc[d][2] * inv_c);
                    v0.w = lrelu(acc[d][3] * inv_c);
                    v1.x = lrelu(acc[d][4] * inv_c);
                    v1.y = lrelu(acc[d][5] * inv_c);
                    v1.z = lrelu(acc[d][6] * inv_c);
                    v1.w = lrelu(acc[d][7] * inv_c);
                    *(float4*)(o)     = v0;
                    *(float4*)(o + 4) = v1;
                }
            }
        }
    }
}

// ---------------- final 3x3 conv (v3: cp.async double-buffer) ---------------
// Block 16x16 threads, tile 32x32, per thread 2x2 px x 2 co.
// All 473-ch weights pre-staged (padded to 480); inputs double-buffered.
#define FIN_SZ (8*34*36)     // floats per input buffer (9792)

__global__ __launch_bounds__(256)
void final_conv_v3(const float* __restrict__ redir, const float* __restrict__ corr,
                   const float* __restrict__ wgt, float* __restrict__ out)
{
    extern __shared__ float smem[];   // [2*FIN_SZ inputs][480*18 weights]
    float* sw = smem + 2*FIN_SZ;      // sw[c*18 + k*2 + o]

    const int x0 = blockIdx.x * 32;
    const int y0 = blockIdx.y * 32;
    const int b  = blockIdx.z;
    const int tx = threadIdx.x, ty = threadIdx.y;
    const int tid = ty*16 + tx;

    uint32_t smem_u32 = (uint32_t)__cvta_generic_to_shared(smem);

    int  soff[5];  int spat[5];
    bool inb[5];   bool wr[5];
#pragma unroll
    for (int k = 0; k < 5; k++) {
        int i = tid + k*256;
        bool ok = (i < 34*34);
        int ii = ok ? i : 0;
        int ly = ii / 34, lx = ii % 34;
        int gy = y0 + ly - 1, gx = x0 + lx - 1;
        bool v = ok && (gy >= 0) && (gy < HH) && (gx >= 0) && (gx < WW);
        soff[k] = ly*36 + lx;
        spat[k] = v ? gy*WW + gx : 0;
        inb[k]  = v;
        wr[k]   = ok;
    }

    // stage one 8-channel chunk (channels c0..c0+7, cn valid)
    auto stage = [&](int buf, int c0) {
        const int cn = (473 - c0) < 8 ? (473 - c0) : 8;
        const float* base = (c0 < 32) ? (redir + (b*32 + c0)*HWW)
                                      : (corr + (b*441 + (c0 - 32))*HWW);
        uint32_t in_dst = smem_u32 + buf*(FIN_SZ*4);
#pragma unroll
        for (int k = 0; k < 5; k++) {
            if (wr[k]) {
                const float* p = base + spat[k];
                uint32_t d = in_dst + soff[k]*4;
#pragma unroll
                for (int c = 0; c < 8; c++)
                    cp_async4(d + c*(34*36*4), p + c*HWW, inb[k] && (c < cn));
            }
        }
        cp_commit();
    };

    stage(0, 0);

    // pre-stage all weights, zero-padded to 480 channels
    for (int i = tid; i < 480*18; i += 256) {
        int c = i / 18, r = i % 18;
        int kk = r >> 1, o = r & 1;
        sw[i] = (c < 473) ? wgt[(o*473 + c)*9 + kk] : 0.f;
    }

    float acc[2][2][2];
#pragma unroll
    for (int o = 0; o < 2; o++)
#pragma unroll
        for (int py = 0; py < 2; py++)
#pragma unroll
            for (int px = 0; px < 2; px++) acc[o][py][px] = 0.f;

    const int NCH = 60;   // ceil(473/8)
    for (int ci = 0; ci < NCH; ci++) {
        cp_wait0();
        __syncthreads();           // also covers the weight staging (ci==0)
        if (ci + 1 < NCH) stage((ci+1) & 1, (ci+1)*8);

        const float* s_in = smem + (ci & 1)*FIN_SZ;
        const float* wb = sw + ci*8*18;

#pragma unroll
        for (int c = 0; c < 8; c++) {
            float p[4][4];
#pragma unroll
            for (int r = 0; r < 4; r++)
#pragma unroll
                for (int q = 0; q < 4; q++)
                    p[r][q] = s_in[c*(34*36) + (ty*2 + r)*36 + tx*2 + q];
#pragma unroll
            for (int ky = 0; ky < 3; ky++) {
#pragma unroll
                for (int kx = 0; kx < 3; kx++) {
                    const float w0 = wb[c*18 + (ky*3+kx)*2 + 0];
                    const float w1 = wb[c*18 + (ky*3+kx)*2 + 1];
#pragma unroll
                    for (int py = 0; py < 2; py++) {
#pragma unroll
                        for (int px = 0; px < 2; px++) {
                            const float v = p[py+ky][px+kx];
                            acc[0][py][px] += v * w0;
                            acc[1][py][px] += v * w1;
                        }
                    }
                }
            }
        }
    }

#pragma unroll
    for (int o = 0; o < 2; o++) {
#pragma unroll
        for (int py = 0; py < 2; py++) {
            const int y = y0 + ty*2 + py;
            const int x = x0 + tx*2;
            float2 v;
            v.x = acc[o][py][0];
            v.y = acc[o][py][1];
            *(float2*)&out[((b*2 + o)*HH + y)*WW + x] = v;
        }
    }
}

// ---------------- launch -----------------------------------------------------
extern "C" void kernel_launch(void* const* d_in, const int* in_sizes, int n_in,
                              void* d_out, int out_size)
{
    const float* pred    = (const float*)d_in[0];
    const float* ref     = (const float*)d_in[1];
    const float* conv1_w = (const float*)d_in[2];
    const float* conv1_b = (const float*)d_in[3];
    const float* conv2_w = (const float*)d_in[4];
    const float* conv2_b = (const float*)d_in[5];
    const float* redir_w = (const float*)d_in[6];
    const float* redir_b = (const float*)d_in[7];
    const float* pred_w  = (const float*)d_in[8];
    float* out = (float*)d_out;

    float *c1a, *c1b, *c2a, *c2b, *rdr, *cor;
    cudaGetSymbolAddress((void**)&c1a, g_c1a);
    cudaGetSymbolAddress((void**)&c1b, g_c1b);
    cudaGetSymbolAddress((void**)&c2a, g_c2a);
    cudaGetSymbolAddress((void**)&c2b, g_c2b);
    cudaGetSymbolAddress((void**)&rdr, g_redir);
    cudaGetSymbolAddress((void**)&cor, g_corr);

    const int conv_smem = (2*SIN4 + 64*72) * (int)sizeof(float); // 57600
    cudaFuncSetAttribute(conv3x3_v4<64,64>,  cudaFuncAttributeMaxDynamicSharedMemorySize, conv_smem);
    cudaFuncSetAttribute(conv3x3_v4<64,128>, cudaFuncAttributeMaxDynamicSharedMemorySize, conv_smem);

    // conv1 (64->64) on pred and ref
    {
        dim3 grid(WW/32, HH/32, BB * (64/8));
        dim3 blk(16, 16);
        conv3x3_v4<64,64><<<grid, blk, conv_smem>>>(pred, conv1_w, conv1_b, c1a);
        conv3x3_v4<64,64><<<grid, blk, conv_smem>>>(ref,  conv1_w, conv1_b, c1b);
    }
    // conv2 (64->128)
    {
        dim3 grid(WW/32, HH/32, BB * (128/8));
        dim3 blk(16, 16);
        conv3x3_v4<64,128><<<grid, blk, conv_smem>>>(c1a, conv2_w, conv2_b, c2a);
        conv3x3_v4<64,128><<<grid, blk, conv_smem>>>(c1b, conv2_w, conv2_b, c2b);
    }
    // redir 1x1 (128->32)
    {
        dim3 grid(HWW/64, BB);
        redir_conv<<<grid, 256>>>(c2a, redir_w, redir_b, rdr);
    }
    // correlation
    {
        const int smem_bytes = (SA_FLOATS + 2*SBUF_FLOATS) * (int)sizeof(float); // 221184
        cudaFuncSetAttribute(corr_v7, cudaFuncAttributeMaxDynamicSharedMemorySize, smem_bytes);
        dim3 grid(HH, BB);
        corr_v7<<<grid, 288, smem_bytes>>>(c2a, c2b, cor);
    }
    // final conv (473->2)
    {
        const int fin_smem = (2*FIN_SZ + 480*18) * (int)sizeof(float); // 112896
        cudaFuncSetAttribute(final_conv_v3, cudaFuncAttributeMaxDynamicSharedMemorySize, fin_smem);
        dim3 grid(WW/32, HH/32, BB);
        dim3 blk(16, 16);
        final_conv_v3<<<grid, blk, fin_smem>>>(rdr, cor, pred_w, out);
    }
}